// round 6
// baseline (speedup 1.0000x reference)
#include <cuda_runtime.h>
#include <cuda_bf16.h>
#include <cstdint>

// ---------------- problem constants ----------------
#define NTOK    4096
#define CDIM    256
#define NH      8
#define HD      32
#define LK      32
#define GB      16
#define NW      64
#define BW      1024
#define MROWS   65536
#define NKEY    48

typedef unsigned long long u64;
typedef __nv_bfloat16 bf16;

// ---------------- device-global scratch ----------------
__device__ __align__(16) float g_q[BW * NH * NW * HD];
__device__ __align__(16) float g_k[BW * NH * NW * HD];
__device__ __align__(16) float g_v[BW * NH * NW * HD];
__device__ __align__(16) bf16  g_xhi[(size_t)MROWS * CDIM];
__device__ __align__(16) bf16  g_xlo[(size_t)MROWS * CDIM];
__device__ __align__(16) bf16  g_aohi[(size_t)MROWS * CDIM];
__device__ __align__(16) bf16  g_aolo[(size_t)MROWS * CDIM];
__device__ __align__(16) bf16  g_wqkvT_hi[768 * 256];
__device__ __align__(16) bf16  g_wqkvT_lo[768 * 256];
__device__ __align__(16) bf16  g_wpT_hi[256 * 256];
__device__ __align__(16) bf16  g_wpT_lo[256 * 256];

// ---------------- helpers ----------------
__device__ __forceinline__ uint32_t smem_u32(const void* p) {
    uint32_t a;
    asm("{ .reg .u64 t; cvta.to.shared.u64 t, %1; cvt.u32.u64 %0, t; }" : "=r"(a) : "l"(p));
    return a;
}
__device__ __forceinline__ u64 pack2(float lo, float hi) {
    u64 d;
    asm("mov.b64 %0, {%1, %2};" : "=l"(d)
        : "r"(__float_as_uint(lo)), "r"(__float_as_uint(hi)));
    return d;
}
__device__ __forceinline__ void unpack2(u64 v, float& lo, float& hi) {
    unsigned int a, b;
    asm("mov.b64 {%0, %1}, %2;" : "=r"(a), "=r"(b) : "l"(v));
    lo = __uint_as_float(a); hi = __uint_as_float(b);
}
__device__ __forceinline__ void fma2(u64& acc, u64 a, u64 b) {
    asm("fma.rn.f32x2 %0, %1, %2, %0;" : "+l"(acc) : "l"(a), "l"(b));
}

// fast exp2 on the fma pipe (no MUFU). |t| <~ 60 assumed. rel err ~2e-6.
__device__ __forceinline__ float fexp2(float t) {
    const float magic = 12582912.0f;            // 1.5 * 2^23
    float r = t + magic;                        // round-to-nearest-int in low bits
    int   i = __float_as_int(r) - 0x4B400000;   // integer part (signed)
    float f = t - (r - magic);                  // f in [-0.5, 0.5]
    float p = 0.00133335581464284f;
    p = fmaf(p, f, 0.00961812910762848f);
    p = fmaf(p, f, 0.0555041086648216f);
    p = fmaf(p, f, 0.240226506959101f);
    p = fmaf(p, f, 0.693147180559945f);
    p = fmaf(p, f, 1.0f);
    return __int_as_float(__float_as_int(p) + (i << 23));
}

__device__ __forceinline__ void cp16(uint32_t saddr, const void* gaddr) {
    asm volatile("cp.async.cg.shared.global [%0], [%1], 16;"
                 :: "r"(saddr), "l"(gaddr));
}
#define CP_COMMIT() asm volatile("cp.async.commit_group;" ::: "memory")
#define CP_WAIT(n)  asm volatile("cp.async.wait_group %0;" :: "n"(n) : "memory")

__device__ __forceinline__ void ldsm4(uint32_t (&r)[4], uint32_t addr) {
    asm volatile("ldmatrix.sync.aligned.m8n8.x4.shared.b16 {%0,%1,%2,%3}, [%4];"
                 : "=r"(r[0]), "=r"(r[1]), "=r"(r[2]), "=r"(r[3]) : "r"(addr));
}
__device__ __forceinline__ void mma16816(float (&d)[4], const uint32_t (&a)[4],
                                         uint32_t b0, uint32_t b1) {
    asm volatile("mma.sync.aligned.m16n8k16.row.col.f32.bf16.bf16.f32 "
                 "{%0,%1,%2,%3}, {%4,%5,%6,%7}, {%8,%9}, {%0,%1,%2,%3};"
                 : "+f"(d[0]), "+f"(d[1]), "+f"(d[2]), "+f"(d[3])
                 : "r"(a[0]), "r"(a[1]), "r"(a[2]), "r"(a[3]), "r"(b0), "r"(b1));
}

// =================================================================================
// conv_x: fp32 x -> window-gathered bf16 hi/lo rows [row][k]
// =================================================================================
__global__ void __launch_bounds__(256) conv_x(const float* __restrict__ x)
{
    const int t   = blockIdx.x * 256 + threadIdx.x;
    const int row = t >> 5;
    const int seg = (t & 31) * 8;
    const int w   = row >> 6, tt = row & 63;
    const int b   = w >> 6,  wrem = w & 63;
    const int gtok = (((wrem >> 3) * 8 + (tt >> 3)) << 6) + ((wrem & 7) * 8 + (tt & 7));
    const float* src = x + ((size_t)(b * NTOK + gtok)) * CDIM + seg;

    float v[8];
    *(float4*)(v)     = *(const float4*)(src);
    *(float4*)(v + 4) = *(const float4*)(src + 4);

    bf16 hs[8], ls[8];
    #pragma unroll
    for (int i = 0; i < 8; i++) {
        hs[i] = __float2bfloat16_rn(v[i]);
        ls[i] = __float2bfloat16_rn(v[i] - __bfloat162float(hs[i]));
    }
    *(uint4*)(g_xhi + (size_t)row * CDIM + seg) = *(uint4*)hs;
    *(uint4*)(g_xlo + (size_t)row * CDIM + seg) = *(uint4*)ls;
}

// =================================================================================
// conv_w: transpose + split W_qkv [256][768] and W_proj [256][256] into [n][k] hi/lo
// =================================================================================
__global__ void __launch_bounds__(64) conv_w(const float* __restrict__ Wqkv,
                                             const float* __restrict__ Wp)
{
    const int n = blockIdx.x;
    for (int k = threadIdx.x; k < CDIM; k += 64) {
        float val; bf16 *dh, *dl;
        if (n < 768) {
            val = Wqkv[(size_t)k * 768 + n];
            dh = g_wqkvT_hi + (size_t)n * CDIM + k;
            dl = g_wqkvT_lo + (size_t)n * CDIM + k;
        } else {
            const int n2 = n - 768;
            val = Wp[(size_t)k * CDIM + n2];
            dh = g_wpT_hi + (size_t)n2 * CDIM + k;
            dl = g_wpT_lo + (size_t)n2 * CDIM + k;
        }
        bf16 h = __float2bfloat16_rn(val);
        *dh = h;
        *dl = __float2bfloat16_rn(val - __bfloat162float(h));
    }
}

// =================================================================================
// HMMA bf16-split GEMM.  BM=128 BN=128 BK=32, 256 thr, warp tile 64x32.
// =================================================================================
#define RS   80
#define AHI  0
#define ALO  10240
#define BHI  20480
#define BLO  30720
#define STG  40960
#define SMEMB (2 * STG)

template<int MODE>
__global__ void __launch_bounds__(256) hmma_gemm(const float* __restrict__ bias,
                                                 float* __restrict__ outp)
{
    extern __shared__ char sm[];
    const uint32_t smb = smem_u32(sm);
    const int tid  = threadIdx.x;
    const int lane = tid & 31, wid = tid >> 5;
    const int warp_m = wid >> 2, warp_n = wid & 3;      // 2 x 4 warps
    const int bx = blockIdx.x, by = blockIdx.y;

    const bf16* Ahi_g = (MODE == 0) ? g_xhi : g_aohi;
    const bf16* Alo_g = (MODE == 0) ? g_xlo : g_aolo;
    const bf16* Bhi_g = (MODE == 0) ? g_wqkvT_hi : g_wpT_hi;
    const bf16* Blo_g = (MODE == 0) ? g_wqkvT_lo : g_wpT_lo;

    const size_t a_base = (size_t)(bx * 128) * CDIM;
    const size_t b_base = (size_t)(by * 128) * CDIM;

    const uint32_t a_frag = (uint32_t)((warp_m * 64 + (lane & 15)) * RS
                                       + (lane >> 4) * 16);
    const uint32_t b_frag = (uint32_t)((warp_n * 32 + (lane & 7) + ((lane >> 4) << 3)) * RS
                                       + ((lane >> 3) & 1) * 16);

    float acc[4][4][4] = {};

    auto stage_load = [&](int s, int kt) {
        const uint32_t sb = smb + s * STG;
        #pragma unroll
        for (int i = 0; i < 2; i++) {
            const int c   = tid + i * 256;
            const int row = c >> 2;
            const int kc  = c & 3;
            const uint32_t so = (uint32_t)(row * RS + kc * 16);
            const size_t   go = (size_t)row * CDIM + (size_t)kt * 32 + kc * 8;
            cp16(sb + AHI + so, Ahi_g + a_base + go);
            cp16(sb + ALO + so, Alo_g + a_base + go);
            cp16(sb + BHI + so, Bhi_g + b_base + go);
            cp16(sb + BLO + so, Blo_g + b_base + go);
        }
    };

    stage_load(0, 0);
    CP_COMMIT();

    #pragma unroll 1
    for (int it = 0; it < 8; it++) {
        if (it < 7) { stage_load((it + 1) & 1, it + 1); CP_COMMIT(); CP_WAIT(1); }
        else        { CP_WAIT(0); }
        __syncthreads();

        const uint32_t st = smb + (it & 1) * STG;
        #pragma unroll
        for (int kk = 0; kk < 2; kk++) {
            uint32_t ahi[4][4], alo[4][4], bhi[4][2], blo[4][2];
            #pragma unroll
            for (int mt = 0; mt < 4; mt++) {
                ldsm4(ahi[mt], st + AHI + a_frag + mt * (16 * RS) + kk * 32);
                ldsm4(alo[mt], st + ALO + a_frag + mt * (16 * RS) + kk * 32);
            }
            #pragma unroll
            for (int np = 0; np < 2; np++) {
                uint32_t th[4], tl[4];
                ldsm4(th, st + BHI + b_frag + np * (16 * RS) + kk * 32);
                ldsm4(tl, st + BLO + b_frag + np * (16 * RS) + kk * 32);
                bhi[np * 2][0] = th[0]; bhi[np * 2][1] = th[1];
                bhi[np * 2 + 1][0] = th[2]; bhi[np * 2 + 1][1] = th[3];
                blo[np * 2][0] = tl[0]; blo[np * 2][1] = tl[1];
                blo[np * 2 + 1][0] = tl[2]; blo[np * 2 + 1][1] = tl[3];
            }
            #pragma unroll
            for (int mt = 0; mt < 4; mt++)
                #pragma unroll
                for (int nt = 0; nt < 4; nt++) {
                    mma16816(acc[mt][nt], ahi[mt], bhi[nt][0], bhi[nt][1]);
                    mma16816(acc[mt][nt], ahi[mt], blo[nt][0], blo[nt][1]);
                    mma16816(acc[mt][nt], alo[mt], bhi[nt][0], bhi[nt][1]);
                }
        }
        __syncthreads();
    }

    // ---------------- epilogue ----------------
    const int w = bx * 2 + warp_m;
    const int qrow = lane >> 2;
    const int qcol = (lane & 3) * 2;

    if (MODE == 0) {
        const int s  = by >> 1;
        float* dst = (s == 0) ? g_q : ((s == 1) ? g_k : g_v);
        const int h = (by & 1) * 4 + warp_n;
        float* hb = dst + (((size_t)(w * NH + h)) << 11);
        #pragma unroll
        for (int nt = 0; nt < 4; nt++) {
            const int d  = nt * 8 + qcol;
            const int jg = by * 128 + warp_n * 32 + d;
            const float2 b2 = *(const float2*)(bias + jg);
            #pragma unroll
            for (int mt = 0; mt < 4; mt++) {
                const int tok = mt * 16 + qrow;
                float2 o0 = make_float2(acc[mt][nt][0] + b2.x, acc[mt][nt][1] + b2.y);
                float2 o1 = make_float2(acc[mt][nt][2] + b2.x, acc[mt][nt][3] + b2.y);
                *(float2*)(hb + ((tok)     << 5) + d) = o0;
                *(float2*)(hb + ((tok + 8) << 5) + d) = o1;
            }
        }
    } else {
        const int b = w >> 6, wrem = w & 63;
        #pragma unroll
        for (int nt = 0; nt < 4; nt++) {
            const int jg = by * 128 + warp_n * 32 + nt * 8 + qcol;
            const float2 b2 = *(const float2*)(bias + jg);
            #pragma unroll
            for (int mt = 0; mt < 4; mt++) {
                #pragma unroll
                for (int half = 0; half < 2; half++) {
                    const int tok = mt * 16 + qrow + half * 8;
                    const int gtok = (((wrem >> 3) * 8 + (tok >> 3)) << 6)
                                   + ((wrem & 7) * 8 + (tok & 7));
                    float2 o = make_float2(acc[mt][nt][half * 2]     + b2.x,
                                           acc[mt][nt][half * 2 + 1] + b2.y);
                    *(float2*)(outp + ((size_t)(b * NTOK + gtok)) * CDIM + jg) = o;
                }
            }
        }
    }
}

// =================================================================================
// attn kernel: per-(window,head), 64 threads; poly-exp (no MUFU); two-phase softmax
// =================================================================================
__global__ void __launch_bounds__(64, 10) attn_kernel(const float* __restrict__ E_k,
                                                      const float* __restrict__ E_v,
                                                      const float* __restrict__ k_bank,
                                                      const float* __restrict__ v_bank)
{
    __shared__ __align__(16) float sKV[NW * HD];
    __shared__ __align__(16) float sE [NW * LK];
    __shared__ __align__(16) float sKc[NKEY * HD];
    __shared__ __align__(16) float sVc[NKEY * HD];

    const int blk = blockIdx.x;
    const int w   = blk >> 3;
    const int h   = blk & 7;
    const int tid = threadIdx.x;
    const size_t base = (size_t)blk * NW * HD;

    const int lg = tid >> 3, dg = tid & 7;
    const int l0 = lg * 4,   d0 = dg * 4;

    for (int sel = 0; sel < 2; sel++) {
        const float* src  = sel ? g_v : g_k;
        const float* E    = sel ? E_v : E_k;
        const float* bank = sel ? v_bank : k_bank;
        float* dstc       = sel ? sVc : sKc;

        {
            const float4* sp = (const float4*)(src + base + tid * HD);
            float4* dp = (float4*)(sKV + tid * HD);
            #pragma unroll
            for (int i = 0; i < 8; i++) dp[i] = sp[i];
            const float4* ep = (const float4*)(E) + tid * 8;
            float4* ed = (float4*)(sE) + tid * 8;
            #pragma unroll
            for (int i = 0; i < 8; i++) ed[i] = ep[i];
        }
        __syncthreads();

        u64 acc[4][2] = {};
        #pragma unroll 4
        for (int nn = 0; nn < NW; nn++) {
            float4 e4 = *(const float4*)&sE[nn * LK + l0];
            ulonglong2 k2 = *(const ulonglong2*)&sKV[nn * HD + d0];
            u64 e0 = pack2(e4.x, e4.x), e1 = pack2(e4.y, e4.y);
            u64 e2 = pack2(e4.z, e4.z), e3 = pack2(e4.w, e4.w);
            fma2(acc[0][0], e0, k2.x); fma2(acc[0][1], e0, k2.y);
            fma2(acc[1][0], e1, k2.x); fma2(acc[1][1], e1, k2.y);
            fma2(acc[2][0], e2, k2.x); fma2(acc[2][1], e2, k2.y);
            fma2(acc[3][0], e3, k2.x); fma2(acc[3][1], e3, k2.y);
        }
        #pragma unroll
        for (int li = 0; li < 4; li++) {
            float f0, f1, f2, f3;
            unpack2(acc[li][0], f0, f1);
            unpack2(acc[li][1], f2, f3);
            *(float4*)&dstc[(l0 + li) * HD + d0] = make_float4(f0, f1, f2, f3);
        }
        #pragma unroll
        for (int i = 0; i < 8; i++) {
            const int idx = tid + i * 64;
            const int g = idx >> 5, d = idx & 31;
            dstc[LK * HD + idx] = __ldg(bank + g * CDIM + h * HD + d);
        }
        __syncthreads();
    }

    // ---------- phase A: scores + exp (poly, fma pipe) ----------
    // scale/sqrt(hd) * log2(e) folded into one constant
    const float SL = 0.17677669529663687f * 1.4426950408889634f;

    float es[NKEY];
    {
        u64 qr[16];
        const ulonglong2* qp = (const ulonglong2*)(g_q + base + tid * HD);
        #pragma unroll
        for (int u = 0; u < 8; u++) {
            ulonglong2 v2 = qp[u];
            qr[2 * u] = v2.x; qr[2 * u + 1] = v2.y;
        }
        #pragma unroll
        for (int j = 0; j < NKEY; j++) {
            const ulonglong2* kp = (const ulonglong2*)&sKc[j * HD];
            u64 s2a = 0, s2b = 0;
            #pragma unroll
            for (int u = 0; u < 8; u++) {
                ulonglong2 kv = kp[u];
                fma2(s2a, qr[2 * u],     kv.x);
                fma2(s2b, qr[2 * u + 1], kv.y);
            }
            float a0, a1, b0, b1;
            unpack2(s2a, a0, a1);
            unpack2(s2b, b0, b1);
            es[j] = fexp2(((a0 + a1) + (b0 + b1)) * SL);
        }
    }

    float denom = 0.f;
    #pragma unroll
    for (int j = 0; j < NKEY; j++) denom += es[j];
    const float inv = 1.f / denom;

    // ---------- phase B: weighted V accumulation ----------
    u64 out2[16] = {};
    #pragma unroll
    for (int j = 0; j < NKEY; j++) {
        const u64 e2 = pack2(es[j], es[j]);
        const ulonglong2* vp = (const ulonglong2*)&sVc[j * HD];
        #pragma unroll
        for (int u = 0; u < 8; u++) {
            ulonglong2 vv = vp[u];
            fma2(out2[2 * u],     e2, vv.x);
            fma2(out2[2 * u + 1], e2, vv.y);
        }
    }

    const size_t rowoff = ((size_t)(w * NW + tid)) * CDIM + h * HD;
    #pragma unroll
    for (int p = 0; p < 4; p++) {
        float vv[8];
        unpack2(out2[4 * p],     vv[0], vv[1]);
        unpack2(out2[4 * p + 1], vv[2], vv[3]);
        unpack2(out2[4 * p + 2], vv[4], vv[5]);
        unpack2(out2[4 * p + 3], vv[6], vv[7]);
        bf16 hs[8], ls[8];
        #pragma unroll
        for (int i = 0; i < 8; i++) {
            const float f = vv[i] * inv;
            hs[i] = __float2bfloat16_rn(f);
            ls[i] = __float2bfloat16_rn(f - __bfloat162float(hs[i]));
        }
        *(uint4*)(g_aohi + rowoff + p * 8) = *(uint4*)hs;
        *(uint4*)(g_aolo + rowoff + p * 8) = *(uint4*)ls;
    }
}

// =================================================================================
extern "C" void kernel_launch(void* const* d_in, const int* in_sizes, int n_in,
                              void* d_out, int out_size)
{
    (void)in_sizes; (void)n_in; (void)out_size;
    const float* x     = (const float*)d_in[0];
    const float* Wqkv  = (const float*)d_in[1];
    const float* bqkv  = (const float*)d_in[2];
    const float* E_k   = (const float*)d_in[3];
    const float* E_v   = (const float*)d_in[4];
    const float* kbank = (const float*)d_in[5];
    const float* vbank = (const float*)d_in[6];
    const float* Wp    = (const float*)d_in[7];
    const float* bp    = (const float*)d_in[8];
    float* out = (float*)d_out;

    cudaFuncSetAttribute(hmma_gemm<0>,
                         cudaFuncAttributeMaxDynamicSharedMemorySize, SMEMB);
    cudaFuncSetAttribute(hmma_gemm<1>,
                         cudaFuncAttributeMaxDynamicSharedMemorySize, SMEMB);

    conv_x<<<8192, 256>>>(x);
    conv_w<<<1024, 64>>>(Wqkv, Wp);
    hmma_gemm<0><<<dim3(512, 6), 256, SMEMB>>>(bqkv, nullptr);
    attn_kernel<<<BW * NH, 64>>>(E_k, E_v, kbank, vbank);
    hmma_gemm<1><<<dim3(512, 2), 256, SMEMB>>>(bp, out);
}

// round 7
// speedup vs baseline: 1.0943x; 1.0943x over previous
#include <cuda_runtime.h>
#include <cuda_bf16.h>
#include <cstdint>

// ---------------- problem constants ----------------
#define NTOK    4096
#define CDIM    256
#define NH      8
#define HD      32
#define LK      32
#define GB      16
#define NW      64
#define BW      1024
#define MROWS   65536
#define NKEY    48

typedef unsigned long long u64;
typedef __nv_bfloat16 bf16;

// ---------------- device-global scratch ----------------
__device__ __align__(16) float g_q[BW * NH * NW * HD];
__device__ __align__(16) float g_k[BW * NH * NW * HD];
__device__ __align__(16) float g_v[BW * NH * NW * HD];
__device__ __align__(16) bf16  g_xhi[(size_t)MROWS * CDIM];
__device__ __align__(16) bf16  g_xlo[(size_t)MROWS * CDIM];
__device__ __align__(16) bf16  g_aohi[(size_t)MROWS * CDIM];
__device__ __align__(16) bf16  g_aolo[(size_t)MROWS * CDIM];
__device__ __align__(16) bf16  g_wqkvT_hi[768 * 256];
__device__ __align__(16) bf16  g_wqkvT_lo[768 * 256];
__device__ __align__(16) bf16  g_wpT_hi[256 * 256];
__device__ __align__(16) bf16  g_wpT_lo[256 * 256];

// ---------------- helpers ----------------
__device__ __forceinline__ uint32_t smem_u32(const void* p) {
    uint32_t a;
    asm("{ .reg .u64 t; cvta.to.shared.u64 t, %1; cvt.u32.u64 %0, t; }" : "=r"(a) : "l"(p));
    return a;
}
__device__ __forceinline__ u64 pack2(float lo, float hi) {
    u64 d;
    asm("mov.b64 %0, {%1, %2};" : "=l"(d)
        : "r"(__float_as_uint(lo)), "r"(__float_as_uint(hi)));
    return d;
}
__device__ __forceinline__ void unpack2(u64 v, float& lo, float& hi) {
    unsigned int a, b;
    asm("mov.b64 {%0, %1}, %2;" : "=r"(a), "=r"(b) : "l"(v));
    lo = __uint_as_float(a); hi = __uint_as_float(b);
}
__device__ __forceinline__ void fma2(u64& acc, u64 a, u64 b) {
    asm("fma.rn.f32x2 %0, %1, %2, %0;" : "+l"(acc) : "l"(a), "l"(b));
}

__device__ __forceinline__ void cp16(uint32_t saddr, const void* gaddr) {
    asm volatile("cp.async.cg.shared.global [%0], [%1], 16;"
                 :: "r"(saddr), "l"(gaddr));
}
#define CP_COMMIT() asm volatile("cp.async.commit_group;" ::: "memory")
#define CP_WAIT(n)  asm volatile("cp.async.wait_group %0;" :: "n"(n) : "memory")

__device__ __forceinline__ void ldsm4(uint32_t (&r)[4], uint32_t addr) {
    asm volatile("ldmatrix.sync.aligned.m8n8.x4.shared.b16 {%0,%1,%2,%3}, [%4];"
                 : "=r"(r[0]), "=r"(r[1]), "=r"(r[2]), "=r"(r[3]) : "r"(addr));
}
__device__ __forceinline__ void mma16816(float (&d)[4], const uint32_t (&a)[4],
                                         uint32_t b0, uint32_t b1) {
    asm volatile("mma.sync.aligned.m16n8k16.row.col.f32.bf16.bf16.f32 "
                 "{%0,%1,%2,%3}, {%4,%5,%6,%7}, {%8,%9}, {%0,%1,%2,%3};"
                 : "+f"(d[0]), "+f"(d[1]), "+f"(d[2]), "+f"(d[3])
                 : "r"(a[0]), "r"(a[1]), "r"(a[2]), "r"(a[3]), "r"(b0), "r"(b1));
}

// =================================================================================
// conv_x: fp32 x -> window-gathered bf16 hi/lo rows [row][k]
// =================================================================================
__global__ void __launch_bounds__(256) conv_x(const float* __restrict__ x)
{
    const int t   = blockIdx.x * 256 + threadIdx.x;
    const int row = t >> 5;
    const int seg = (t & 31) * 8;
    const int w   = row >> 6, tt = row & 63;
    const int b   = w >> 6,  wrem = w & 63;
    const int gtok = (((wrem >> 3) * 8 + (tt >> 3)) << 6) + ((wrem & 7) * 8 + (tt & 7));
    const float* src = x + ((size_t)(b * NTOK + gtok)) * CDIM + seg;

    float v[8];
    *(float4*)(v)     = *(const float4*)(src);
    *(float4*)(v + 4) = *(const float4*)(src + 4);

    bf16 hs[8], ls[8];
    #pragma unroll
    for (int i = 0; i < 8; i++) {
        hs[i] = __float2bfloat16_rn(v[i]);
        ls[i] = __float2bfloat16_rn(v[i] - __bfloat162float(hs[i]));
    }
    *(uint4*)(g_xhi + (size_t)row * CDIM + seg) = *(uint4*)hs;
    *(uint4*)(g_xlo + (size_t)row * CDIM + seg) = *(uint4*)ls;
}

// =================================================================================
// conv_w: transpose + split W_qkv [256][768] and W_proj [256][256] into [n][k] hi/lo
// =================================================================================
__global__ void __launch_bounds__(64) conv_w(const float* __restrict__ Wqkv,
                                             const float* __restrict__ Wp)
{
    const int n = blockIdx.x;
    for (int k = threadIdx.x; k < CDIM; k += 64) {
        float val; bf16 *dh, *dl;
        if (n < 768) {
            val = Wqkv[(size_t)k * 768 + n];
            dh = g_wqkvT_hi + (size_t)n * CDIM + k;
            dl = g_wqkvT_lo + (size_t)n * CDIM + k;
        } else {
            const int n2 = n - 768;
            val = Wp[(size_t)k * CDIM + n2];
            dh = g_wpT_hi + (size_t)n2 * CDIM + k;
            dl = g_wpT_lo + (size_t)n2 * CDIM + k;
        }
        bf16 h = __float2bfloat16_rn(val);
        *dh = h;
        *dl = __float2bfloat16_rn(val - __bfloat162float(h));
    }
}

// =================================================================================
// HMMA bf16-split GEMM.  BM=128 BN=128 BK=32, 256 thr, warp tile 64x32.
// =================================================================================
#define RS   80
#define AHI  0
#define ALO  10240
#define BHI  20480
#define BLO  30720
#define STG  40960
#define SMEMB (2 * STG)

template<int MODE>
__global__ void __launch_bounds__(256) hmma_gemm(const float* __restrict__ bias,
                                                 float* __restrict__ outp)
{
    extern __shared__ char sm[];
    const uint32_t smb = smem_u32(sm);
    const int tid  = threadIdx.x;
    const int lane = tid & 31, wid = tid >> 5;
    const int warp_m = wid >> 2, warp_n = wid & 3;      // 2 x 4 warps
    const int bx = blockIdx.x, by = blockIdx.y;

    const bf16* Ahi_g = (MODE == 0) ? g_xhi : g_aohi;
    const bf16* Alo_g = (MODE == 0) ? g_xlo : g_aolo;
    const bf16* Bhi_g = (MODE == 0) ? g_wqkvT_hi : g_wpT_hi;
    const bf16* Blo_g = (MODE == 0) ? g_wqkvT_lo : g_wpT_lo;

    const size_t a_base = (size_t)(bx * 128) * CDIM;
    const size_t b_base = (size_t)(by * 128) * CDIM;

    const uint32_t a_frag = (uint32_t)((warp_m * 64 + (lane & 15)) * RS
                                       + (lane >> 4) * 16);
    const uint32_t b_frag = (uint32_t)((warp_n * 32 + (lane & 7) + ((lane >> 4) << 3)) * RS
                                       + ((lane >> 3) & 1) * 16);

    float acc[4][4][4] = {};

    auto stage_load = [&](int s, int kt) {
        const uint32_t sb = smb + s * STG;
        #pragma unroll
        for (int i = 0; i < 2; i++) {
            const int c   = tid + i * 256;
            const int row = c >> 2;
            const int kc  = c & 3;
            const uint32_t so = (uint32_t)(row * RS + kc * 16);
            const size_t   go = (size_t)row * CDIM + (size_t)kt * 32 + kc * 8;
            cp16(sb + AHI + so, Ahi_g + a_base + go);
            cp16(sb + ALO + so, Alo_g + a_base + go);
            cp16(sb + BHI + so, Bhi_g + b_base + go);
            cp16(sb + BLO + so, Blo_g + b_base + go);
        }
    };

    stage_load(0, 0);
    CP_COMMIT();

    #pragma unroll 1
    for (int it = 0; it < 8; it++) {
        if (it < 7) { stage_load((it + 1) & 1, it + 1); CP_COMMIT(); CP_WAIT(1); }
        else        { CP_WAIT(0); }
        __syncthreads();

        const uint32_t st = smb + (it & 1) * STG;
        #pragma unroll
        for (int kk = 0; kk < 2; kk++) {
            uint32_t ahi[4][4], alo[4][4], bhi[4][2], blo[4][2];
            #pragma unroll
            for (int mt = 0; mt < 4; mt++) {
                ldsm4(ahi[mt], st + AHI + a_frag + mt * (16 * RS) + kk * 32);
                ldsm4(alo[mt], st + ALO + a_frag + mt * (16 * RS) + kk * 32);
            }
            #pragma unroll
            for (int np = 0; np < 2; np++) {
                uint32_t th[4], tl[4];
                ldsm4(th, st + BHI + b_frag + np * (16 * RS) + kk * 32);
                ldsm4(tl, st + BLO + b_frag + np * (16 * RS) + kk * 32);
                bhi[np * 2][0] = th[0]; bhi[np * 2][1] = th[1];
                bhi[np * 2 + 1][0] = th[2]; bhi[np * 2 + 1][1] = th[3];
                blo[np * 2][0] = tl[0]; blo[np * 2][1] = tl[1];
                blo[np * 2 + 1][0] = tl[2]; blo[np * 2 + 1][1] = tl[3];
            }
            #pragma unroll
            for (int mt = 0; mt < 4; mt++)
                #pragma unroll
                for (int nt = 0; nt < 4; nt++) {
                    mma16816(acc[mt][nt], ahi[mt], bhi[nt][0], bhi[nt][1]);
                    mma16816(acc[mt][nt], ahi[mt], blo[nt][0], blo[nt][1]);
                    mma16816(acc[mt][nt], alo[mt], bhi[nt][0], bhi[nt][1]);
                }
        }
        __syncthreads();
    }

    // ---------------- epilogue ----------------
    const int w = bx * 2 + warp_m;
    const int qrow = lane >> 2;
    const int qcol = (lane & 3) * 2;

    if (MODE == 0) {
        const int s  = by >> 1;
        float* dst = (s == 0) ? g_q : ((s == 1) ? g_k : g_v);
        const int h = (by & 1) * 4 + warp_n;
        float* hb = dst + (((size_t)(w * NH + h)) << 11);
        #pragma unroll
        for (int nt = 0; nt < 4; nt++) {
            const int d  = nt * 8 + qcol;
            const int jg = by * 128 + warp_n * 32 + d;
            const float2 b2 = *(const float2*)(bias + jg);
            #pragma unroll
            for (int mt = 0; mt < 4; mt++) {
                const int tok = mt * 16 + qrow;
                float2 o0 = make_float2(acc[mt][nt][0] + b2.x, acc[mt][nt][1] + b2.y);
                float2 o1 = make_float2(acc[mt][nt][2] + b2.x, acc[mt][nt][3] + b2.y);
                *(float2*)(hb + ((tok)     << 5) + d) = o0;
                *(float2*)(hb + ((tok + 8) << 5) + d) = o1;
            }
        }
    } else {
        const int b = w >> 6, wrem = w & 63;
        #pragma unroll
        for (int nt = 0; nt < 4; nt++) {
            const int jg = by * 128 + warp_n * 32 + nt * 8 + qcol;
            const float2 b2 = *(const float2*)(bias + jg);
            #pragma unroll
            for (int mt = 0; mt < 4; mt++) {
                #pragma unroll
                for (int half = 0; half < 2; half++) {
                    const int tok = mt * 16 + qrow + half * 8;
                    const int gtok = (((wrem >> 3) * 8 + (tok >> 3)) << 6)
                                   + ((wrem & 7) * 8 + (tok & 7));
                    float2 o = make_float2(acc[mt][nt][half * 2]     + b2.x,
                                           acc[mt][nt][half * 2 + 1] + b2.y);
                    *(float2*)(outp + ((size_t)(b * NTOK + gtok)) * CDIM + jg) = o;
                }
            }
        }
    }
}

// =================================================================================
// attn kernel: one block = one window x 2 heads, 256 threads.
//   - sE shared across both heads; both heads compressed in one loop (E reuse)
//   - softmax: 2 threads per query (16 dims each), shfl.xor(1) combines halves
// =================================================================================
__global__ void __launch_bounds__(256, 4) attn_kernel(const float* __restrict__ E_k,
                                                      const float* __restrict__ E_v,
                                                      const float* __restrict__ k_bank,
                                                      const float* __restrict__ v_bank)
{
    __shared__ __align__(16) float sE  [NW * LK];        // 8KB
    __shared__ __align__(16) float sKVa[NW * HD];        // 8KB
    __shared__ __align__(16) float sKVb[NW * HD];        // 8KB
    __shared__ __align__(16) float sKc [2][NKEY * HD];   // 12KB
    __shared__ __align__(16) float sVc [2][NKEY * HD];   // 12KB

    const int blk = blockIdx.x;
    const int w   = blk >> 2;
    const int h0  = (blk & 3) * 2;
    const int tid = threadIdx.x;

    const float* gk0 = g_k + ((size_t)(w * NH + h0)) * (NW * HD);
    const float* gv0 = g_v + ((size_t)(w * NH + h0)) * (NW * HD);

    const int cl = tid >> 3;            // 0..31 : compressed row l
    const int cd = (tid & 7) * 4;       // d group

    for (int sel = 0; sel < 2; sel++) {
        const float* E    = sel ? E_v : E_k;
        const float* s0   = sel ? gv0 : gk0;
        const float* bank = sel ? v_bank : k_bank;
        float (*dst)[NKEY * HD] = sel ? sVc : sKc;

        // stage E + both heads' K/V tiles (512 float4 each)
        #pragma unroll
        for (int i = 0; i < 2; i++) {
            const int idx = tid + i * 256;
            ((float4*)sE)[idx]   = ((const float4*)E)[idx];
            ((float4*)sKVa)[idx] = ((const float4*)s0)[idx];
            ((float4*)sKVb)[idx] = ((const float4*)(s0 + NW * HD))[idx];
        }
        // bank rows: 2 heads x 16 g x 32 d = 1024 floats = 256 float4
        {
            const int hh = tid >> 7, rem = tid & 127;
            const int g = rem >> 3, dq = (rem & 7) * 4;
            *(float4*)&dst[hh][(LK + g) * HD + dq] =
                *(const float4*)(bank + g * CDIM + (h0 + hh) * HD + dq);
        }
        __syncthreads();

        // compress both heads with shared E read
        u64 a0 = 0, a1 = 0, b0 = 0, b1 = 0;
        #pragma unroll 8
        for (int nn = 0; nn < NW; nn++) {
            const float e = sE[nn * LK + cl];
            const u64 eu = pack2(e, e);
            ulonglong2 ka = *(const ulonglong2*)&sKVa[nn * HD + cd];
            ulonglong2 kb = *(const ulonglong2*)&sKVb[nn * HD + cd];
            fma2(a0, eu, ka.x); fma2(a1, eu, ka.y);
            fma2(b0, eu, kb.x); fma2(b1, eu, kb.y);
        }
        float f0, f1, f2, f3;
        unpack2(a0, f0, f1); unpack2(a1, f2, f3);
        *(float4*)&dst[0][cl * HD + cd] = make_float4(f0, f1, f2, f3);
        unpack2(b0, f0, f1); unpack2(b1, f2, f3);
        *(float4*)&dst[1][cl * HD + cd] = make_float4(f0, f1, f2, f3);
        __syncthreads();
    }

    // ---------------- softmax: thread = (hh, q, s) ----------------
    const int s  = tid & 1;
    const int q  = (tid >> 1) & 63;
    const int hh = tid >> 7;

    u64 qr[8];
    {
        const ulonglong2* qp = (const ulonglong2*)
            (g_q + ((size_t)(w * NH + h0 + hh) * NW + q) * HD + s * 16);
        #pragma unroll
        for (int u = 0; u < 4; u++) {
            ulonglong2 t2 = qp[u];
            qr[2 * u] = t2.x; qr[2 * u + 1] = t2.y;
        }
    }

    const float scale = 0.17677669529663687f;   // 1/sqrt(32)
    const float* kcb = sKc[hh] + s * 16;
    const float* vcb = sVc[hh] + s * 16;

    u64 out2[8] = {};
    float denom = 0.f;
    #pragma unroll 4
    for (int j = 0; j < NKEY; j++) {
        const ulonglong2* kp = (const ulonglong2*)(kcb + j * HD);
        u64 sa = 0, sb = 0;
        #pragma unroll
        for (int u = 0; u < 4; u++) {
            ulonglong2 kv = kp[u];
            fma2(sa, qr[2 * u],     kv.x);
            fma2(sb, qr[2 * u + 1], kv.y);
        }
        float p0, p1, p2, p3;
        unpack2(sa, p0, p1); unpack2(sb, p2, p3);
        float part = (p0 + p1) + (p2 + p3);
        part += __shfl_xor_sync(0xFFFFFFFFu, part, 1);
        const float e = __expf(part * scale);
        denom += e;
        const u64 e2 = pack2(e, e);
        const ulonglong2* vp = (const ulonglong2*)(vcb + j * HD);
        #pragma unroll
        for (int u = 0; u < 4; u++) {
            ulonglong2 vv = vp[u];
            fma2(out2[2 * u],     e2, vv.x);
            fma2(out2[2 * u + 1], e2, vv.y);
        }
    }
    const float inv = 1.f / denom;

    const size_t rowoff = ((size_t)(w * NW + q)) * CDIM + (h0 + hh) * HD + s * 16;
    bf16 hs[16], ls[16];
    #pragma unroll
    for (int u = 0; u < 8; u++) {
        float x0, x1;
        unpack2(out2[u], x0, x1);
        x0 *= inv; x1 *= inv;
        hs[2 * u]     = __float2bfloat16_rn(x0);
        ls[2 * u]     = __float2bfloat16_rn(x0 - __bfloat162float(hs[2 * u]));
        hs[2 * u + 1] = __float2bfloat16_rn(x1);
        ls[2 * u + 1] = __float2bfloat16_rn(x1 - __bfloat162float(hs[2 * u + 1]));
    }
    *(uint4*)(g_aohi + rowoff)     = *(uint4*)hs;
    *(uint4*)(g_aohi + rowoff + 8) = *(uint4*)(hs + 8);
    *(uint4*)(g_aolo + rowoff)     = *(uint4*)ls;
    *(uint4*)(g_aolo + rowoff + 8) = *(uint4*)(ls + 8);
}

// =================================================================================
extern "C" void kernel_launch(void* const* d_in, const int* in_sizes, int n_in,
                              void* d_out, int out_size)
{
    (void)in_sizes; (void)n_in; (void)out_size;
    const float* x     = (const float*)d_in[0];
    const float* Wqkv  = (const float*)d_in[1];
    const float* bqkv  = (const float*)d_in[2];
    const float* E_k   = (const float*)d_in[3];
    const float* E_v   = (const float*)d_in[4];
    const float* kbank = (const float*)d_in[5];
    const float* vbank = (const float*)d_in[6];
    const float* Wp    = (const float*)d_in[7];
    const float* bp    = (const float*)d_in[8];
    float* out = (float*)d_out;

    cudaFuncSetAttribute(hmma_gemm<0>,
                         cudaFuncAttributeMaxDynamicSharedMemorySize, SMEMB);
    cudaFuncSetAttribute(hmma_gemm<1>,
                         cudaFuncAttributeMaxDynamicSharedMemorySize, SMEMB);

    conv_x<<<8192, 256>>>(x);
    conv_w<<<1024, 64>>>(Wqkv, Wp);
    hmma_gemm<0><<<dim3(512, 6), 256, SMEMB>>>(bqkv, nullptr);
    attn_kernel<<<BW * 4, 256>>>(E_k, E_v, kbank, vbank);
    hmma_gemm<1><<<dim3(512, 2), 256, SMEMB>>>(bp, out);
}

// round 9
// speedup vs baseline: 1.4133x; 1.2915x over previous
#include <cuda_runtime.h>
#include <cuda_bf16.h>
#include <cstdint>

// ---------------- problem constants ----------------
#define NTOK    4096
#define CDIM    256
#define NH      8
#define HD      32
#define LK      32
#define GB      16
#define NW      64
#define BW      1024
#define MROWS   65536
#define NKEY    48

typedef unsigned long long u64;
typedef __nv_bfloat16 bf16;

// ---------------- device-global scratch ----------------
__device__ __align__(16) bf16  g_qhi[(size_t)BW * NH * NW * HD];
__device__ __align__(16) bf16  g_qlo[(size_t)BW * NH * NW * HD];
__device__ __align__(16) bf16  g_khi[(size_t)BW * NH * NW * HD];
__device__ __align__(16) bf16  g_klo[(size_t)BW * NH * NW * HD];
__device__ __align__(16) bf16  g_vhi[(size_t)BW * NH * NW * HD];
__device__ __align__(16) bf16  g_vlo[(size_t)BW * NH * NW * HD];
__device__ __align__(16) bf16  g_xhi[(size_t)MROWS * CDIM];
__device__ __align__(16) bf16  g_xlo[(size_t)MROWS * CDIM];
__device__ __align__(16) bf16  g_aohi[(size_t)MROWS * CDIM];
__device__ __align__(16) bf16  g_aolo[(size_t)MROWS * CDIM];
__device__ __align__(16) bf16  g_wqkvT_hi[768 * 256];
__device__ __align__(16) bf16  g_wqkvT_lo[768 * 256];
__device__ __align__(16) bf16  g_wpT_hi[256 * 256];
__device__ __align__(16) bf16  g_wpT_lo[256 * 256];
__device__ __align__(16) bf16  g_ekThi[LK * NW];   // E_k^T [l][n]
__device__ __align__(16) bf16  g_ekTlo[LK * NW];
__device__ __align__(16) bf16  g_evThi[LK * NW];
__device__ __align__(16) bf16  g_evTlo[LK * NW];

// ---------------- helpers ----------------
__device__ __forceinline__ uint32_t smem_u32(const void* p) {
    uint32_t a;
    asm("{ .reg .u64 t; cvta.to.shared.u64 t, %1; cvt.u32.u64 %0, t; }" : "=r"(a) : "l"(p));
    return a;
}
__device__ __forceinline__ void cp16(uint32_t saddr, const void* gaddr) {
    asm volatile("cp.async.cg.shared.global [%0], [%1], 16;"
                 :: "r"(saddr), "l"(gaddr));
}
#define CP_COMMIT() asm volatile("cp.async.commit_group;" ::: "memory")
#define CP_WAIT(n)  asm volatile("cp.async.wait_group %0;" :: "n"(n) : "memory")

__device__ __forceinline__ void ldsm4(uint32_t (&r)[4], uint32_t addr) {
    asm volatile("ldmatrix.sync.aligned.m8n8.x4.shared.b16 {%0,%1,%2,%3}, [%4];"
                 : "=r"(r[0]), "=r"(r[1]), "=r"(r[2]), "=r"(r[3]) : "r"(addr));
}
__device__ __forceinline__ void ldsm4t(uint32_t (&r)[4], uint32_t addr) {
    asm volatile("ldmatrix.sync.aligned.m8n8.x4.trans.shared.b16 {%0,%1,%2,%3}, [%4];"
                 : "=r"(r[0]), "=r"(r[1]), "=r"(r[2]), "=r"(r[3]) : "r"(addr));
}
__device__ __forceinline__ void mma16816(float (&d)[4], const uint32_t (&a)[4],
                                         uint32_t b0, uint32_t b1) {
    asm volatile("mma.sync.aligned.m16n8k16.row.col.f32.bf16.bf16.f32 "
                 "{%0,%1,%2,%3}, {%4,%5,%6,%7}, {%8,%9}, {%0,%1,%2,%3};"
                 : "+f"(d[0]), "+f"(d[1]), "+f"(d[2]), "+f"(d[3])
                 : "r"(a[0]), "r"(a[1]), "r"(a[2]), "r"(a[3]), "r"(b0), "r"(b1));
}
__device__ __forceinline__ void mma3(float (&d)[4], const uint32_t (&ah)[4],
                                     const uint32_t (&al)[4],
                                     uint32_t bh0, uint32_t bh1,
                                     uint32_t bl0, uint32_t bl1) {
    mma16816(d, ah, bh0, bh1);
    mma16816(d, ah, bl0, bl1);
    mma16816(d, al, bh0, bh1);
}
__device__ __forceinline__ void split2(float x, float y, uint32_t& hi, uint32_t& lo) {
    __nv_bfloat162 h = __floats2bfloat162_rn(x, y);
    float rx = x - __bfloat162float(h.x);
    float ry = y - __bfloat162float(h.y);
    __nv_bfloat162 l = __floats2bfloat162_rn(rx, ry);
    hi = *(uint32_t*)&h;
    lo = *(uint32_t*)&l;
}

// =================================================================================
// conv_x: fp32 x -> window-gathered bf16 hi/lo rows [row][k]
// =================================================================================
__global__ void __launch_bounds__(256) conv_x(const float* __restrict__ x)
{
    const int t   = blockIdx.x * 256 + threadIdx.x;
    const int row = t >> 5;
    const int seg = (t & 31) * 8;
    const int w   = row >> 6, tt = row & 63;
    const int b   = w >> 6,  wrem = w & 63;
    const int gtok = (((wrem >> 3) * 8 + (tt >> 3)) << 6) + ((wrem & 7) * 8 + (tt & 7));
    const float* src = x + ((size_t)(b * NTOK + gtok)) * CDIM + seg;

    float v[8];
    *(float4*)(v)     = *(const float4*)(src);
    *(float4*)(v + 4) = *(const float4*)(src + 4);

    bf16 hs[8], ls[8];
    #pragma unroll
    for (int i = 0; i < 8; i++) {
        hs[i] = __float2bfloat16_rn(v[i]);
        ls[i] = __float2bfloat16_rn(v[i] - __bfloat162float(hs[i]));
    }
    *(uint4*)(g_xhi + (size_t)row * CDIM + seg) = *(uint4*)hs;
    *(uint4*)(g_xlo + (size_t)row * CDIM + seg) = *(uint4*)ls;
}

// =================================================================================
// conv_w: transpose + split W_qkv and W_proj into [n][k] hi/lo
// =================================================================================
__global__ void __launch_bounds__(64) conv_w(const float* __restrict__ Wqkv,
                                             const float* __restrict__ Wp)
{
    const int n = blockIdx.x;
    for (int k = threadIdx.x; k < CDIM; k += 64) {
        float val; bf16 *dh, *dl;
        if (n < 768) {
            val = Wqkv[(size_t)k * 768 + n];
            dh = g_wqkvT_hi + (size_t)n * CDIM + k;
            dl = g_wqkvT_lo + (size_t)n * CDIM + k;
        } else {
            const int n2 = n - 768;
            val = Wp[(size_t)k * CDIM + n2];
            dh = g_wpT_hi + (size_t)n2 * CDIM + k;
            dl = g_wpT_lo + (size_t)n2 * CDIM + k;
        }
        bf16 h = __float2bfloat16_rn(val);
        *dh = h;
        *dl = __float2bfloat16_rn(val - __bfloat162float(h));
    }
}

// =================================================================================
// conv_eT: E_k/E_v [64][32] -> E^T [32][64] bf16 hi/lo
// =================================================================================
__global__ void __launch_bounds__(128) conv_eT(const float* __restrict__ Ek,
                                               const float* __restrict__ Ev)
{
    const int t = blockIdx.x * 128 + threadIdx.x;   // 0..2047
    const int l = t >> 6, n = t & 63;
    float vk = Ek[n * LK + l];
    float vv = Ev[n * LK + l];
    bf16 hk = __float2bfloat16_rn(vk);
    bf16 hv = __float2bfloat16_rn(vv);
    g_ekThi[t] = hk;
    g_ekTlo[t] = __float2bfloat16_rn(vk - __bfloat162float(hk));
    g_evThi[t] = hv;
    g_evTlo[t] = __float2bfloat16_rn(vv - __bfloat162float(hv));
}

// =================================================================================
// HMMA bf16-split GEMM.  BM=128 BN=128 BK=32, 256 thr, warp tile 64x32.
//   MODE 0: qkv -> writes q/k/v as bf16 hi/lo (q pre-scaled by 1/sqrt(hd))
//   MODE 1: proj -> window-reverse fp32 out + bias
// =================================================================================
#define RS   80
#define AHI  0
#define ALO  10240
#define BHI  20480
#define BLO  30720
#define STG  40960
#define SMEMB (2 * STG)

template<int MODE>
__global__ void __launch_bounds__(256) hmma_gemm(const float* __restrict__ bias,
                                                 float* __restrict__ outp)
{
    extern __shared__ char sm[];
    const uint32_t smb = smem_u32(sm);
    const int tid  = threadIdx.x;
    const int lane = tid & 31, wid = tid >> 5;
    const int warp_m = wid >> 2, warp_n = wid & 3;
    const int bx = blockIdx.x, by = blockIdx.y;

    const bf16* Ahi_g = (MODE == 0) ? g_xhi : g_aohi;
    const bf16* Alo_g = (MODE == 0) ? g_xlo : g_aolo;
    const bf16* Bhi_g = (MODE == 0) ? g_wqkvT_hi : g_wpT_hi;
    const bf16* Blo_g = (MODE == 0) ? g_wqkvT_lo : g_wpT_lo;

    const size_t a_base = (size_t)(bx * 128) * CDIM;
    const size_t b_base = (size_t)(by * 128) * CDIM;

    const uint32_t a_frag = (uint32_t)((warp_m * 64 + (lane & 15)) * RS
                                       + (lane >> 4) * 16);
    const uint32_t b_frag = (uint32_t)((warp_n * 32 + (lane & 7) + ((lane >> 4) << 3)) * RS
                                       + ((lane >> 3) & 1) * 16);

    float acc[4][4][4] = {};

    auto stage_load = [&](int s, int kt) {
        const uint32_t sb = smb + s * STG;
        #pragma unroll
        for (int i = 0; i < 2; i++) {
            const int c   = tid + i * 256;
            const int row = c >> 2;
            const int kc  = c & 3;
            const uint32_t so = (uint32_t)(row * RS + kc * 16);
            const size_t   go = (size_t)row * CDIM + (size_t)kt * 32 + kc * 8;
            cp16(sb + AHI + so, Ahi_g + a_base + go);
            cp16(sb + ALO + so, Alo_g + a_base + go);
            cp16(sb + BHI + so, Bhi_g + b_base + go);
            cp16(sb + BLO + so, Blo_g + b_base + go);
        }
    };

    stage_load(0, 0);
    CP_COMMIT();

    #pragma unroll 1
    for (int it = 0; it < 8; it++) {
        if (it < 7) { stage_load((it + 1) & 1, it + 1); CP_COMMIT(); CP_WAIT(1); }
        else        { CP_WAIT(0); }
        __syncthreads();

        const uint32_t st = smb + (it & 1) * STG;
        #pragma unroll
        for (int kk = 0; kk < 2; kk++) {
            uint32_t ahi[4][4], alo[4][4], bhi[4][2], blo[4][2];
            #pragma unroll
            for (int mt = 0; mt < 4; mt++) {
                ldsm4(ahi[mt], st + AHI + a_frag + mt * (16 * RS) + kk * 32);
                ldsm4(alo[mt], st + ALO + a_frag + mt * (16 * RS) + kk * 32);
            }
            #pragma unroll
            for (int np = 0; np < 2; np++) {
                uint32_t th[4], tl[4];
                ldsm4(th, st + BHI + b_frag + np * (16 * RS) + kk * 32);
                ldsm4(tl, st + BLO + b_frag + np * (16 * RS) + kk * 32);
                bhi[np * 2][0] = th[0]; bhi[np * 2][1] = th[1];
                bhi[np * 2 + 1][0] = th[2]; bhi[np * 2 + 1][1] = th[3];
                blo[np * 2][0] = tl[0]; blo[np * 2][1] = tl[1];
                blo[np * 2 + 1][0] = tl[2]; blo[np * 2 + 1][1] = tl[3];
            }
            #pragma unroll
            for (int mt = 0; mt < 4; mt++)
                #pragma unroll
                for (int nt = 0; nt < 4; nt++) {
                    mma16816(acc[mt][nt], ahi[mt], bhi[nt][0], bhi[nt][1]);
                    mma16816(acc[mt][nt], ahi[mt], blo[nt][0], blo[nt][1]);
                    mma16816(acc[mt][nt], alo[mt], bhi[nt][0], bhi[nt][1]);
                }
        }
        __syncthreads();
    }

    // ---------------- epilogue ----------------
    const int w = bx * 2 + warp_m;
    const int qrow = lane >> 2;
    const int qcol = (lane & 3) * 2;

    if (MODE == 0) {
        const int s  = by >> 1;                       // 0=q,1=k,2=v
        bf16* dhi = (s == 0) ? g_qhi : ((s == 1) ? g_khi : g_vhi);
        bf16* dlo = (s == 0) ? g_qlo : ((s == 1) ? g_klo : g_vlo);
        const float qs = (s == 0) ? 0.17677669529663687f : 1.0f;
        const int h = (by & 1) * 4 + warp_n;
        const size_t hb = ((size_t)(w * NH + h)) << 11;
        #pragma unroll
        for (int nt = 0; nt < 4; nt++) {
            const int d  = nt * 8 + qcol;
            const int jg = by * 128 + warp_n * 32 + d;
            const float2 b2 = *(const float2*)(bias + jg);
            #pragma unroll
            for (int mt = 0; mt < 4; mt++) {
                const int tok = mt * 16 + qrow;
                uint32_t h0, l0, h1, l1;
                split2((acc[mt][nt][0] + b2.x) * qs, (acc[mt][nt][1] + b2.y) * qs, h0, l0);
                split2((acc[mt][nt][2] + b2.x) * qs, (acc[mt][nt][3] + b2.y) * qs, h1, l1);
                *(uint32_t*)(dhi + hb + ((size_t)tok << 5) + d)       = h0;
                *(uint32_t*)(dlo + hb + ((size_t)tok << 5) + d)       = l0;
                *(uint32_t*)(dhi + hb + ((size_t)(tok + 8) << 5) + d) = h1;
                *(uint32_t*)(dlo + hb + ((size_t)(tok + 8) << 5) + d) = l1;
            }
        }
    } else {
        const int b = w >> 6, wrem = w & 63;
        #pragma unroll
        for (int nt = 0; nt < 4; nt++) {
            const int jg = by * 128 + warp_n * 32 + nt * 8 + qcol;
            const float2 b2 = *(const float2*)(bias + jg);
            #pragma unroll
            for (int mt = 0; mt < 4; mt++) {
                #pragma unroll
                for (int half = 0; half < 2; half++) {
                    const int tok = mt * 16 + qrow + half * 8;
                    const int gtok = (((wrem >> 3) * 8 + (tok >> 3)) << 6)
                                   + ((wrem & 7) * 8 + (tok & 7));
                    float2 o = make_float2(acc[mt][nt][half * 2]     + b2.x,
                                           acc[mt][nt][half * 2 + 1] + b2.y);
                    *(float2*)(outp + ((size_t)(b * NTOK + gtok)) * CDIM + jg) = o;
                }
            }
        }
    }
}

// =================================================================================
// HMMA attention: block = (window, 2 heads), 64 threads, warp = head.
//   All per-warp buffers use 80B row stride (16B-aligned, conflict-free ldmatrix).
// =================================================================================
#define ET_SZ   4608                 // 32 rows * 144B (row = 128B data + pad)
#define ARS     80                   // attn row stride
#define W_STGH  0                    // [64][80B] hi
#define W_STGL  5120                 // [64][80B] lo
#define W_KCH   10240                // [48][80B]
#define W_KCL   14080
#define W_VCH   17920
#define W_VCL   21760
#define W_SZ    25600
#define ATTN_SM (4 * ET_SZ + 2 * W_SZ)   // 18432 + 51200 = 69632

__global__ void __launch_bounds__(64) attn_kernel(const float* __restrict__ k_bank,
                                                  const float* __restrict__ v_bank)
{
    extern __shared__ char sm[];
    const uint32_t smb = smem_u32(sm);
    const int tid  = threadIdx.x;
    const int lane = tid & 31, wid = tid >> 5;
    const int blk  = blockIdx.x;
    const int w    = blk >> 2;
    const int h    = (blk & 3) * 2 + wid;

    // ---- stage E^T matrices (block cooperative): 4 mats x 256 uint4
    {
        const bf16* srcs[4] = { g_ekThi, g_ekTlo, g_evThi, g_evTlo };
        #pragma unroll
        for (int i = 0; i < 16; i++) {
            const int idx = tid + i * 64;           // 0..1023
            const int mat = idx >> 8;
            const int r   = (idx & 255) >> 3;
            const int c   = idx & 7;
            *(uint4*)(sm + mat * ET_SZ + r * 144 + c * 16) =
                *(const uint4*)(srcs[mat] + r * 64 + c * 8);
        }
    }
    __syncthreads();

    char* wbp = sm + 4 * ET_SZ + wid * W_SZ;
    const uint32_t wbu    = smb + 4 * ET_SZ + wid * W_SZ;
    const uint32_t stg_hi = wbu + W_STGH;
    const uint32_t stg_lo = wbu + W_STGL;
    const uint32_t kc_hi  = wbu + W_KCH, kc_lo = wbu + W_KCL;
    const uint32_t vc_hi  = wbu + W_VCH, vc_lo = wbu + W_VCL;

    const size_t qkvoff = ((size_t)(w * NH + h)) << 11;    // *2048 elems
    const int r  = lane >> 2;
    const int c2 = (lane & 3) * 2;

    // ================= compression: K then V =================
    #pragma unroll 1
    for (int sel = 0; sel < 2; sel++) {
        const bf16* shi = sel ? g_vhi : g_khi;
        const bf16* slo = sel ? g_vlo : g_klo;
        const float* bank = sel ? v_bank : k_bank;
        char* ccp_hi = wbp + (sel ? W_VCH : W_KCH);
        char* ccp_lo = wbp + (sel ? W_VCL : W_KCL);
        const uint32_t ehi = smb + (sel ? 2 : 0) * ET_SZ;
        const uint32_t elo = smb + (sel ? 3 : 1) * ET_SZ;

        // stage raw tile [64][32] bf16 hi/lo (80B rows)
        #pragma unroll
        for (int i = 0; i < 8; i++) {
            const int idx = lane + i * 32;          // 0..255 (16B chunks)
            const int rr = idx >> 2, cc = idx & 3;
            *(uint4*)(wbp + W_STGH + rr * ARS + cc * 16) =
                *(const uint4*)(shi + qkvoff + idx * 8);
            *(uint4*)(wbp + W_STGL + rr * ARS + cc * 16) =
                *(const uint4*)(slo + qkvoff + idx * 8);
        }
        // bank rows -> compressed rows 32..47
        {
            const int g  = lane >> 1;
            const int d0 = (lane & 1) * 16;
            float bv[16];
            #pragma unroll
            for (int i = 0; i < 4; i++)
                *(float4*)(bv + i * 4) =
                    *(const float4*)(bank + g * CDIM + h * HD + d0 + i * 4);
            #pragma unroll
            for (int i = 0; i < 8; i++) {
                uint32_t hi, lo;
                split2(bv[2 * i], bv[2 * i + 1], hi, lo);
                *(uint32_t*)(ccp_hi + (32 + g) * ARS + (d0 + 2 * i) * 2) = hi;
                *(uint32_t*)(ccp_lo + (32 + g) * ARS + (d0 + 2 * i) * 2) = lo;
            }
        }
        __syncwarp();

        // Kc = E^T @ K : M=32(l) N=32(d) K=64(t)
        float acc[2][4][4] = {};
        #pragma unroll
        for (int kt = 0; kt < 4; kt++) {
            uint32_t Ah[2][4], Al[2][4], Bh[2][4], Bl[2][4];
            #pragma unroll
            for (int mt = 0; mt < 2; mt++) {
                const uint32_t ao = (uint32_t)((mt * 16 + (lane & 15)) * 144
                                               + kt * 32 + (lane >> 4) * 16);
                ldsm4(Ah[mt], ehi + ao);
                ldsm4(Al[mt], elo + ao);
            }
            const uint32_t to = (uint32_t)((kt * 16 + (lane & 7) + ((lane >> 3) & 1) * 8) * ARS
                                           + (lane >> 4) * 16);
            #pragma unroll
            for (int dg = 0; dg < 2; dg++) {
                ldsm4t(Bh[dg], stg_hi + to + dg * 32);
                ldsm4t(Bl[dg], stg_lo + to + dg * 32);
            }
            #pragma unroll
            for (int mt = 0; mt < 2; mt++)
                #pragma unroll
                for (int dg = 0; dg < 2; dg++) {
                    mma3(acc[mt][dg * 2],     Ah[mt], Al[mt],
                         Bh[dg][0], Bh[dg][1], Bl[dg][0], Bl[dg][1]);
                    mma3(acc[mt][dg * 2 + 1], Ah[mt], Al[mt],
                         Bh[dg][2], Bh[dg][3], Bl[dg][2], Bl[dg][3]);
                }
        }
        // store compressed rows 0..31
        #pragma unroll
        for (int mt = 0; mt < 2; mt++)
            #pragma unroll
            for (int nt = 0; nt < 4; nt++) {
                const int d = nt * 8 + c2;
                uint32_t h0, l0, h1, l1;
                split2(acc[mt][nt][0], acc[mt][nt][1], h0, l0);
                split2(acc[mt][nt][2], acc[mt][nt][3], h1, l1);
                *(uint32_t*)(ccp_hi + (mt * 16 + r) * ARS + d * 2)     = h0;
                *(uint32_t*)(ccp_lo + (mt * 16 + r) * ARS + d * 2)     = l0;
                *(uint32_t*)(ccp_hi + (mt * 16 + r + 8) * ARS + d * 2) = h1;
                *(uint32_t*)(ccp_lo + (mt * 16 + r + 8) * ARS + d * 2) = l1;
            }
        __syncwarp();
    }

    // ================= stage Q (pre-scaled in qkv epilogue) =================
    #pragma unroll
    for (int i = 0; i < 8; i++) {
        const int idx = lane + i * 32;
        const int rr = idx >> 2, cc = idx & 3;
        *(uint4*)(wbp + W_STGH + rr * ARS + cc * 16) =
            *(const uint4*)(g_qhi + qkvoff + idx * 8);
        *(uint4*)(wbp + W_STGL + rr * ARS + cc * 16) =
            *(const uint4*)(g_qlo + qkvoff + idx * 8);
    }
    __syncwarp();

    // ================= QK: M=64 N=48 K=32 =================
    float S[4][6][4] = {};
    #pragma unroll
    for (int kd = 0; kd < 2; kd++) {
        uint32_t Qh[4][4], Ql[4][4], Kh[3][4], Kl[3][4];
        #pragma unroll
        for (int mt = 0; mt < 4; mt++) {
            const uint32_t ao = (uint32_t)((mt * 16 + (lane & 15)) * ARS
                                           + kd * 32 + (lane >> 4) * 16);
            ldsm4(Qh[mt], stg_hi + ao);
            ldsm4(Ql[mt], stg_lo + ao);
        }
        const uint32_t bo = (uint32_t)(((lane & 7) + ((lane >> 4) << 3)) * ARS
                                       + ((lane >> 3) & 1) * 16 + kd * 32);
        #pragma unroll
        for (int jg = 0; jg < 3; jg++) {
            ldsm4(Kh[jg], kc_hi + jg * (16 * ARS) + bo);
            ldsm4(Kl[jg], kc_lo + jg * (16 * ARS) + bo);
        }
        #pragma unroll
        for (int mt = 0; mt < 4; mt++)
            #pragma unroll
            for (int jg = 0; jg < 3; jg++) {
                mma3(S[mt][jg * 2],     Qh[mt], Ql[mt],
                     Kh[jg][0], Kh[jg][1], Kl[jg][0], Kl[jg][1]);
                mma3(S[mt][jg * 2 + 1], Qh[mt], Ql[mt],
                     Kh[jg][2], Kh[jg][3], Kl[jg][2], Kl[jg][3]);
            }
    }

    // ================= softmax (no max subtraction; scores O(1)) =================
    float invA[4], invB[4];
    #pragma unroll
    for (int mt = 0; mt < 4; mt++) {
        float sA = 0.f, sB = 0.f;
        #pragma unroll
        for (int nt = 0; nt < 6; nt++) {
            S[mt][nt][0] = __expf(S[mt][nt][0]);
            S[mt][nt][1] = __expf(S[mt][nt][1]);
            S[mt][nt][2] = __expf(S[mt][nt][2]);
            S[mt][nt][3] = __expf(S[mt][nt][3]);
            sA += S[mt][nt][0] + S[mt][nt][1];
            sB += S[mt][nt][2] + S[mt][nt][3];
        }
        sA += __shfl_xor_sync(0xFFFFFFFFu, sA, 1);
        sA += __shfl_xor_sync(0xFFFFFFFFu, sA, 2);
        sB += __shfl_xor_sync(0xFFFFFFFFu, sB, 1);
        sB += __shfl_xor_sync(0xFFFFFFFFu, sB, 2);
        invA[mt] = 1.f / sA;
        invB[mt] = 1.f / sB;
    }

    // ================= PV: M=64 N=32 K=48 =================
    float O[4][4][4] = {};
    #pragma unroll
    for (int jg = 0; jg < 3; jg++) {
        uint32_t Ph[4][4], Pl[4][4];
        #pragma unroll
        for (int mt = 0; mt < 4; mt++) {
            split2(S[mt][2 * jg][0],     S[mt][2 * jg][1],     Ph[mt][0], Pl[mt][0]);
            split2(S[mt][2 * jg][2],     S[mt][2 * jg][3],     Ph[mt][1], Pl[mt][1]);
            split2(S[mt][2 * jg + 1][0], S[mt][2 * jg + 1][1], Ph[mt][2], Pl[mt][2]);
            split2(S[mt][2 * jg + 1][2], S[mt][2 * jg + 1][3], Ph[mt][3], Pl[mt][3]);
        }
        uint32_t Vh[2][4], Vl[2][4];
        const uint32_t vo = (uint32_t)((jg * 16 + (lane & 7) + ((lane >> 3) & 1) * 8) * ARS
                                       + (lane >> 4) * 16);
        #pragma unroll
        for (int dg = 0; dg < 2; dg++) {
            ldsm4t(Vh[dg], vc_hi + vo + dg * 32);
            ldsm4t(Vl[dg], vc_lo + vo + dg * 32);
        }
        #pragma unroll
        for (int mt = 0; mt < 4; mt++)
            #pragma unroll
            for (int dg = 0; dg < 2; dg++) {
                mma3(O[mt][dg * 2],     Ph[mt], Pl[mt],
                     Vh[dg][0], Vh[dg][1], Vl[dg][0], Vl[dg][1]);
                mma3(O[mt][dg * 2 + 1], Ph[mt], Pl[mt],
                     Vh[dg][2], Vh[dg][3], Vl[dg][2], Vl[dg][3]);
            }
    }

    // ================= normalize + out via smem restage (144B rows) =================
    __syncwarp();
    #pragma unroll
    for (int mt = 0; mt < 4; mt++)
        #pragma unroll
        for (int nt = 0; nt < 4; nt++) {
            const int cc = nt * 8 + c2;
            *(float2*)(wbp + (mt * 16 + r) * 144 + cc * 4) =
                make_float2(O[mt][nt][0] * invA[mt], O[mt][nt][1] * invA[mt]);
            *(float2*)(wbp + (mt * 16 + r + 8) * 144 + cc * 4) =
                make_float2(O[mt][nt][2] * invB[mt], O[mt][nt][3] * invB[mt]);
        }
    __syncwarp();
    #pragma unroll
    for (int rr = 0; rr < 2; rr++) {
        const int r2 = lane + rr * 32;
        float v[32];
        #pragma unroll
        for (int i = 0; i < 8; i++)
            *(float4*)(v + i * 4) = *(const float4*)(wbp + r2 * 144 + i * 16);
        uint32_t hw[16], lw[16];
        #pragma unroll
        for (int i = 0; i < 16; i++)
            split2(v[2 * i], v[2 * i + 1], hw[i], lw[i]);
        const size_t off = ((size_t)(w * NW + r2)) * CDIM + h * HD;
        #pragma unroll
        for (int i = 0; i < 4; i++) {
            *(uint4*)(g_aohi + off + i * 8) = *(uint4*)(hw + i * 4);
            *(uint4*)(g_aolo + off + i * 8) = *(uint4*)(lw + i * 4);
        }
    }
}

// =================================================================================
extern "C" void kernel_launch(void* const* d_in, const int* in_sizes, int n_in,
                              void* d_out, int out_size)
{
    (void)in_sizes; (void)n_in; (void)out_size;
    const float* x     = (const float*)d_in[0];
    const float* Wqkv  = (const float*)d_in[1];
    const float* bqkv  = (const float*)d_in[2];
    const float* E_k   = (const float*)d_in[3];
    const float* E_v   = (const float*)d_in[4];
    const float* kbank = (const float*)d_in[5];
    const float* vbank = (const float*)d_in[6];
    const float* Wp    = (const float*)d_in[7];
    const float* bp    = (const float*)d_in[8];
    float* out = (float*)d_out;

    cudaFuncSetAttribute(hmma_gemm<0>,
                         cudaFuncAttributeMaxDynamicSharedMemorySize, SMEMB);
    cudaFuncSetAttribute(hmma_gemm<1>,
                         cudaFuncAttributeMaxDynamicSharedMemorySize, SMEMB);
    cudaFuncSetAttribute(attn_kernel,
                         cudaFuncAttributeMaxDynamicSharedMemorySize, ATTN_SM);

    conv_x<<<8192, 256>>>(x);
    conv_w<<<1024, 64>>>(Wqkv, Wp);
    conv_eT<<<16, 128>>>(E_k, E_v);
    hmma_gemm<0><<<dim3(512, 6), 256, SMEMB>>>(bqkv, nullptr);
    attn_kernel<<<BW * 4, 64, ATTN_SM>>>(kbank, vbank);
    hmma_gemm<1><<<dim3(512, 2), 256, SMEMB>>>(bp, out);
}

// round 10
// speedup vs baseline: 1.4228x; 1.0067x over previous
#include <cuda_runtime.h>
#include <cuda_bf16.h>
#include <cstdint>

// ---------------- problem constants ----------------
#define NTOK    4096
#define CDIM    256
#define NH      8
#define HD      32
#define LK      32
#define GB      16
#define NW      64
#define BW      1024
#define MROWS   65536
#define NKEY    48

typedef unsigned long long u64;
typedef __nv_bfloat16 bf16;

// ---------------- device-global scratch ----------------
__device__ __align__(16) bf16  g_qhi[(size_t)BW * NH * NW * HD];
__device__ __align__(16) bf16  g_qlo[(size_t)BW * NH * NW * HD];
__device__ __align__(16) bf16  g_khi[(size_t)BW * NH * NW * HD];
__device__ __align__(16) bf16  g_klo[(size_t)BW * NH * NW * HD];
__device__ __align__(16) bf16  g_vhi[(size_t)BW * NH * NW * HD];
__device__ __align__(16) bf16  g_vlo[(size_t)BW * NH * NW * HD];
__device__ __align__(16) bf16  g_xhi[(size_t)MROWS * CDIM];
__device__ __align__(16) bf16  g_xlo[(size_t)MROWS * CDIM];
__device__ __align__(16) bf16  g_aohi[(size_t)MROWS * CDIM];
__device__ __align__(16) bf16  g_aolo[(size_t)MROWS * CDIM];
__device__ __align__(16) bf16  g_wqkvT_hi[768 * 256];
__device__ __align__(16) bf16  g_wqkvT_lo[768 * 256];
__device__ __align__(16) bf16  g_wpT_hi[256 * 256];
__device__ __align__(16) bf16  g_wpT_lo[256 * 256];
__device__ __align__(16) bf16  g_ekThi[LK * NW];   // E_k^T [l][n]
__device__ __align__(16) bf16  g_ekTlo[LK * NW];
__device__ __align__(16) bf16  g_evThi[LK * NW];
__device__ __align__(16) bf16  g_evTlo[LK * NW];

// ---------------- helpers ----------------
__device__ __forceinline__ uint32_t smem_u32(const void* p) {
    uint32_t a;
    asm("{ .reg .u64 t; cvta.to.shared.u64 t, %1; cvt.u32.u64 %0, t; }" : "=r"(a) : "l"(p));
    return a;
}
__device__ __forceinline__ void cp16(uint32_t saddr, const void* gaddr) {
    asm volatile("cp.async.cg.shared.global [%0], [%1], 16;"
                 :: "r"(saddr), "l"(gaddr));
}
#define CP_COMMIT() asm volatile("cp.async.commit_group;" ::: "memory")
#define CP_WAIT(n)  asm volatile("cp.async.wait_group %0;" :: "n"(n) : "memory")

__device__ __forceinline__ void ldsm4(uint32_t (&r)[4], uint32_t addr) {
    asm volatile("ldmatrix.sync.aligned.m8n8.x4.shared.b16 {%0,%1,%2,%3}, [%4];"
                 : "=r"(r[0]), "=r"(r[1]), "=r"(r[2]), "=r"(r[3]) : "r"(addr));
}
__device__ __forceinline__ void ldsm4t(uint32_t (&r)[4], uint32_t addr) {
    asm volatile("ldmatrix.sync.aligned.m8n8.x4.trans.shared.b16 {%0,%1,%2,%3}, [%4];"
                 : "=r"(r[0]), "=r"(r[1]), "=r"(r[2]), "=r"(r[3]) : "r"(addr));
}
__device__ __forceinline__ void mma16816(float (&d)[4], const uint32_t (&a)[4],
                                         uint32_t b0, uint32_t b1) {
    asm volatile("mma.sync.aligned.m16n8k16.row.col.f32.bf16.bf16.f32 "
                 "{%0,%1,%2,%3}, {%4,%5,%6,%7}, {%8,%9}, {%0,%1,%2,%3};"
                 : "+f"(d[0]), "+f"(d[1]), "+f"(d[2]), "+f"(d[3])
                 : "r"(a[0]), "r"(a[1]), "r"(a[2]), "r"(a[3]), "r"(b0), "r"(b1));
}
__device__ __forceinline__ void mma3(float (&d)[4], const uint32_t (&ah)[4],
                                     const uint32_t (&al)[4],
                                     uint32_t bh0, uint32_t bh1,
                                     uint32_t bl0, uint32_t bl1) {
    mma16816(d, ah, bh0, bh1);
    mma16816(d, ah, bl0, bl1);
    mma16816(d, al, bh0, bh1);
}
__device__ __forceinline__ void split2(float x, float y, uint32_t& hi, uint32_t& lo) {
    __nv_bfloat162 h = __floats2bfloat162_rn(x, y);
    float rx = x - __bfloat162float(h.x);
    float ry = y - __bfloat162float(h.y);
    __nv_bfloat162 l = __floats2bfloat162_rn(rx, ry);
    hi = *(uint32_t*)&h;
    lo = *(uint32_t*)&l;
}

// =================================================================================
// conv_x: fp32 x -> window-gathered bf16 hi/lo rows [row][k]
// =================================================================================
__global__ void __launch_bounds__(256) conv_x(const float* __restrict__ x)
{
    const int t   = blockIdx.x * 256 + threadIdx.x;
    const int row = t >> 5;
    const int seg = (t & 31) * 8;
    const int w   = row >> 6, tt = row & 63;
    const int b   = w >> 6,  wrem = w & 63;
    const int gtok = (((wrem >> 3) * 8 + (tt >> 3)) << 6) + ((wrem & 7) * 8 + (tt & 7));
    const float* src = x + ((size_t)(b * NTOK + gtok)) * CDIM + seg;

    float v[8];
    *(float4*)(v)     = *(const float4*)(src);
    *(float4*)(v + 4) = *(const float4*)(src + 4);

    bf16 hs[8], ls[8];
    #pragma unroll
    for (int i = 0; i < 8; i++) {
        hs[i] = __float2bfloat16_rn(v[i]);
        ls[i] = __float2bfloat16_rn(v[i] - __bfloat162float(hs[i]));
    }
    *(uint4*)(g_xhi + (size_t)row * CDIM + seg) = *(uint4*)hs;
    *(uint4*)(g_xlo + (size_t)row * CDIM + seg) = *(uint4*)ls;
}

// =================================================================================
// conv_w: transpose + split W_qkv and W_proj into [n][k] hi/lo
// =================================================================================
__global__ void __launch_bounds__(64) conv_w(const float* __restrict__ Wqkv,
                                             const float* __restrict__ Wp)
{
    const int n = blockIdx.x;
    for (int k = threadIdx.x; k < CDIM; k += 64) {
        float val; bf16 *dh, *dl;
        if (n < 768) {
            val = Wqkv[(size_t)k * 768 + n];
            dh = g_wqkvT_hi + (size_t)n * CDIM + k;
            dl = g_wqkvT_lo + (size_t)n * CDIM + k;
        } else {
            const int n2 = n - 768;
            val = Wp[(size_t)k * CDIM + n2];
            dh = g_wpT_hi + (size_t)n2 * CDIM + k;
            dl = g_wpT_lo + (size_t)n2 * CDIM + k;
        }
        bf16 h = __float2bfloat16_rn(val);
        *dh = h;
        *dl = __float2bfloat16_rn(val - __bfloat162float(h));
    }
}

// =================================================================================
// conv_eT: E_k/E_v [64][32] -> E^T [32][64] bf16 hi/lo
// =================================================================================
__global__ void __launch_bounds__(128) conv_eT(const float* __restrict__ Ek,
                                               const float* __restrict__ Ev)
{
    const int t = blockIdx.x * 128 + threadIdx.x;   // 0..2047
    const int l = t >> 6, n = t & 63;
    float vk = Ek[n * LK + l];
    float vv = Ev[n * LK + l];
    bf16 hk = __float2bfloat16_rn(vk);
    bf16 hv = __float2bfloat16_rn(vv);
    g_ekThi[t] = hk;
    g_ekTlo[t] = __float2bfloat16_rn(vk - __bfloat162float(hk));
    g_evThi[t] = hv;
    g_evTlo[t] = __float2bfloat16_rn(vv - __bfloat162float(hv));
}

// =================================================================================
// HMMA bf16-split GEMM.  BM=128 BN=128 BK=32, 256 thr, warp tile 64x32.
//   Grid launched (NT, 512): blockIdx.x = N-tile (fast axis) so concurrently
//   scheduled blocks share the SAME A M-tile -> A read once from DRAM, rest L2.
//   MODE 0: qkv -> writes q/k/v as bf16 hi/lo (q pre-scaled by 1/sqrt(hd))
//   MODE 1: proj -> window-reverse fp32 out + bias
// =================================================================================
#define RS   80
#define AHI  0
#define ALO  10240
#define BHI  20480
#define BLO  30720
#define STG  40960
#define SMEMB (2 * STG)

template<int MODE>
__global__ void __launch_bounds__(256) hmma_gemm(const float* __restrict__ bias,
                                                 float* __restrict__ outp)
{
    extern __shared__ char sm[];
    const uint32_t smb = smem_u32(sm);
    const int tid  = threadIdx.x;
    const int lane = tid & 31, wid = tid >> 5;
    const int warp_m = wid >> 2, warp_n = wid & 3;
    const int bx = blockIdx.y;          // M-tile (slow axis)
    const int by = blockIdx.x;          // N-tile (fast axis -> A reuse in L2)

    const bf16* Ahi_g = (MODE == 0) ? g_xhi : g_aohi;
    const bf16* Alo_g = (MODE == 0) ? g_xlo : g_aolo;
    const bf16* Bhi_g = (MODE == 0) ? g_wqkvT_hi : g_wpT_hi;
    const bf16* Blo_g = (MODE == 0) ? g_wqkvT_lo : g_wpT_lo;

    const size_t a_base = (size_t)(bx * 128) * CDIM;
    const size_t b_base = (size_t)(by * 128) * CDIM;

    const uint32_t a_frag = (uint32_t)((warp_m * 64 + (lane & 15)) * RS
                                       + (lane >> 4) * 16);
    const uint32_t b_frag = (uint32_t)((warp_n * 32 + (lane & 7) + ((lane >> 4) << 3)) * RS
                                       + ((lane >> 3) & 1) * 16);

    float acc[4][4][4] = {};

    auto stage_load = [&](int s, int kt) {
        const uint32_t sb = smb + s * STG;
        #pragma unroll
        for (int i = 0; i < 2; i++) {
            const int c   = tid + i * 256;
            const int row = c >> 2;
            const int kc  = c & 3;
            const uint32_t so = (uint32_t)(row * RS + kc * 16);
            const size_t   go = (size_t)row * CDIM + (size_t)kt * 32 + kc * 8;
            cp16(sb + AHI + so, Ahi_g + a_base + go);
            cp16(sb + ALO + so, Alo_g + a_base + go);
            cp16(sb + BHI + so, Bhi_g + b_base + go);
            cp16(sb + BLO + so, Blo_g + b_base + go);
        }
    };

    stage_load(0, 0);
    CP_COMMIT();

    #pragma unroll 1
    for (int it = 0; it < 8; it++) {
        if (it < 7) { stage_load((it + 1) & 1, it + 1); CP_COMMIT(); CP_WAIT(1); }
        else        { CP_WAIT(0); }
        __syncthreads();

        const uint32_t st = smb + (it & 1) * STG;
        #pragma unroll
        for (int kk = 0; kk < 2; kk++) {
            uint32_t ahi[4][4], alo[4][4], bhi[4][2], blo[4][2];
            #pragma unroll
            for (int mt = 0; mt < 4; mt++) {
                ldsm4(ahi[mt], st + AHI + a_frag + mt * (16 * RS) + kk * 32);
                ldsm4(alo[mt], st + ALO + a_frag + mt * (16 * RS) + kk * 32);
            }
            #pragma unroll
            for (int np = 0; np < 2; np++) {
                uint32_t th[4], tl[4];
                ldsm4(th, st + BHI + b_frag + np * (16 * RS) + kk * 32);
                ldsm4(tl, st + BLO + b_frag + np * (16 * RS) + kk * 32);
                bhi[np * 2][0] = th[0]; bhi[np * 2][1] = th[1];
                bhi[np * 2 + 1][0] = th[2]; bhi[np * 2 + 1][1] = th[3];
                blo[np * 2][0] = tl[0]; blo[np * 2][1] = tl[1];
                blo[np * 2 + 1][0] = tl[2]; blo[np * 2 + 1][1] = tl[3];
            }
            #pragma unroll
            for (int mt = 0; mt < 4; mt++)
                #pragma unroll
                for (int nt = 0; nt < 4; nt++) {
                    mma16816(acc[mt][nt], ahi[mt], bhi[nt][0], bhi[nt][1]);
                    mma16816(acc[mt][nt], ahi[mt], blo[nt][0], blo[nt][1]);
                    mma16816(acc[mt][nt], alo[mt], bhi[nt][0], bhi[nt][1]);
                }
        }
        __syncthreads();
    }

    // ---------------- epilogue ----------------
    const int w = bx * 2 + warp_m;
    const int qrow = lane >> 2;
    const int qcol = (lane & 3) * 2;

    if (MODE == 0) {
        const int s  = by >> 1;                       // 0=q,1=k,2=v
        bf16* dhi = (s == 0) ? g_qhi : ((s == 1) ? g_khi : g_vhi);
        bf16* dlo = (s == 0) ? g_qlo : ((s == 1) ? g_klo : g_vlo);
        const float qs = (s == 0) ? 0.17677669529663687f : 1.0f;
        const int h = (by & 1) * 4 + warp_n;
        const size_t hb = ((size_t)(w * NH + h)) << 11;
        #pragma unroll
        for (int nt = 0; nt < 4; nt++) {
            const int d  = nt * 8 + qcol;
            const int jg = by * 128 + warp_n * 32 + d;
            const float2 b2 = *(const float2*)(bias + jg);
            #pragma unroll
            for (int mt = 0; mt < 4; mt++) {
                const int tok = mt * 16 + qrow;
                uint32_t h0, l0, h1, l1;
                split2((acc[mt][nt][0] + b2.x) * qs, (acc[mt][nt][1] + b2.y) * qs, h0, l0);
                split2((acc[mt][nt][2] + b2.x) * qs, (acc[mt][nt][3] + b2.y) * qs, h1, l1);
                *(uint32_t*)(dhi + hb + ((size_t)tok << 5) + d)       = h0;
                *(uint32_t*)(dlo + hb + ((size_t)tok << 5) + d)       = l0;
                *(uint32_t*)(dhi + hb + ((size_t)(tok + 8) << 5) + d) = h1;
                *(uint32_t*)(dlo + hb + ((size_t)(tok + 8) << 5) + d) = l1;
            }
        }
    } else {
        const int b = w >> 6, wrem = w & 63;
        #pragma unroll
        for (int nt = 0; nt < 4; nt++) {
            const int jg = by * 128 + warp_n * 32 + nt * 8 + qcol;
            const float2 b2 = *(const float2*)(bias + jg);
            #pragma unroll
            for (int mt = 0; mt < 4; mt++) {
                #pragma unroll
                for (int half = 0; half < 2; half++) {
                    const int tok = mt * 16 + qrow + half * 8;
                    const int gtok = (((wrem >> 3) * 8 + (tok >> 3)) << 6)
                                   + ((wrem & 7) * 8 + (tok & 7));
                    float2 o = make_float2(acc[mt][nt][half * 2]     + b2.x,
                                           acc[mt][nt][half * 2 + 1] + b2.y);
                    *(float2*)(outp + ((size_t)(b * NTOK + gtok)) * CDIM + jg) = o;
                }
            }
        }
    }
}

// =================================================================================
// HMMA attention: block = (window, 2 heads), 64 threads, warp = head.
//   All per-warp buffers use 80B row stride (16B-aligned, conflict-free ldmatrix).
// =================================================================================
#define ET_SZ   4608                 // 32 rows * 144B (row = 128B data + pad)
#define ARS     80                   // attn row stride
#define W_STGH  0                    // [64][80B] hi
#define W_STGL  5120                 // [64][80B] lo
#define W_KCH   10240                // [48][80B]
#define W_KCL   14080
#define W_VCH   17920
#define W_VCL   21760
#define W_SZ    25600
#define ATTN_SM (4 * ET_SZ + 2 * W_SZ)   // 18432 + 51200 = 69632

__global__ void __launch_bounds__(64) attn_kernel(const float* __restrict__ k_bank,
                                                  const float* __restrict__ v_bank)
{
    extern __shared__ char sm[];
    const uint32_t smb = smem_u32(sm);
    const int tid  = threadIdx.x;
    const int lane = tid & 31, wid = tid >> 5;
    const int blk  = blockIdx.x;
    const int w    = blk >> 2;
    const int h    = (blk & 3) * 2 + wid;

    // ---- stage E^T matrices (block cooperative): 4 mats x 256 uint4
    {
        const bf16* srcs[4] = { g_ekThi, g_ekTlo, g_evThi, g_evTlo };
        #pragma unroll
        for (int i = 0; i < 16; i++) {
            const int idx = tid + i * 64;           // 0..1023
            const int mat = idx >> 8;
            const int r   = (idx & 255) >> 3;
            const int c   = idx & 7;
            *(uint4*)(sm + mat * ET_SZ + r * 144 + c * 16) =
                *(const uint4*)(srcs[mat] + r * 64 + c * 8);
        }
    }
    __syncthreads();

    char* wbp = sm + 4 * ET_SZ + wid * W_SZ;
    const uint32_t wbu    = smb + 4 * ET_SZ + wid * W_SZ;
    const uint32_t stg_hi = wbu + W_STGH;
    const uint32_t stg_lo = wbu + W_STGL;
    const uint32_t kc_hi  = wbu + W_KCH, kc_lo = wbu + W_KCL;
    const uint32_t vc_hi  = wbu + W_VCH, vc_lo = wbu + W_VCL;

    const size_t qkvoff = ((size_t)(w * NH + h)) << 11;    // *2048 elems
    const int r  = lane >> 2;
    const int c2 = (lane & 3) * 2;

    // ================= compression: K then V =================
    #pragma unroll 1
    for (int sel = 0; sel < 2; sel++) {
        const bf16* shi = sel ? g_vhi : g_khi;
        const bf16* slo = sel ? g_vlo : g_klo;
        const float* bank = sel ? v_bank : k_bank;
        char* ccp_hi = wbp + (sel ? W_VCH : W_KCH);
        char* ccp_lo = wbp + (sel ? W_VCL : W_KCL);
        const uint32_t ehi = smb + (sel ? 2 : 0) * ET_SZ;
        const uint32_t elo = smb + (sel ? 3 : 1) * ET_SZ;

        // stage raw tile [64][32] bf16 hi/lo (80B rows)
        #pragma unroll
        for (int i = 0; i < 8; i++) {
            const int idx = lane + i * 32;          // 0..255 (16B chunks)
            const int rr = idx >> 2, cc = idx & 3;
            *(uint4*)(wbp + W_STGH + rr * ARS + cc * 16) =
                *(const uint4*)(shi + qkvoff + idx * 8);
            *(uint4*)(wbp + W_STGL + rr * ARS + cc * 16) =
                *(const uint4*)(slo + qkvoff + idx * 8);
        }
        // bank rows -> compressed rows 32..47
        {
            const int g  = lane >> 1;
            const int d0 = (lane & 1) * 16;
            float bv[16];
            #pragma unroll
            for (int i = 0; i < 4; i++)
                *(float4*)(bv + i * 4) =
                    *(const float4*)(bank + g * CDIM + h * HD + d0 + i * 4);
            #pragma unroll
            for (int i = 0; i < 8; i++) {
                uint32_t hi, lo;
                split2(bv[2 * i], bv[2 * i + 1], hi, lo);
                *(uint32_t*)(ccp_hi + (32 + g) * ARS + (d0 + 2 * i) * 2) = hi;
                *(uint32_t*)(ccp_lo + (32 + g) * ARS + (d0 + 2 * i) * 2) = lo;
            }
        }
        __syncwarp();

        // Kc = E^T @ K : M=32(l) N=32(d) K=64(t)
        float acc[2][4][4] = {};
        #pragma unroll
        for (int kt = 0; kt < 4; kt++) {
            uint32_t Ah[2][4], Al[2][4], Bh[2][4], Bl[2][4];
            #pragma unroll
            for (int mt = 0; mt < 2; mt++) {
                const uint32_t ao = (uint32_t)((mt * 16 + (lane & 15)) * 144
                                               + kt * 32 + (lane >> 4) * 16);
                ldsm4(Ah[mt], ehi + ao);
                ldsm4(Al[mt], elo + ao);
            }
            const uint32_t to = (uint32_t)((kt * 16 + (lane & 7) + ((lane >> 3) & 1) * 8) * ARS
                                           + (lane >> 4) * 16);
            #pragma unroll
            for (int dg = 0; dg < 2; dg++) {
                ldsm4t(Bh[dg], stg_hi + to + dg * 32);
                ldsm4t(Bl[dg], stg_lo + to + dg * 32);
            }
            #pragma unroll
            for (int mt = 0; mt < 2; mt++)
                #pragma unroll
                for (int dg = 0; dg < 2; dg++) {
                    mma3(acc[mt][dg * 2],     Ah[mt], Al[mt],
                         Bh[dg][0], Bh[dg][1], Bl[dg][0], Bl[dg][1]);
                    mma3(acc[mt][dg * 2 + 1], Ah[mt], Al[mt],
                         Bh[dg][2], Bh[dg][3], Bl[dg][2], Bl[dg][3]);
                }
        }
        // store compressed rows 0..31
        #pragma unroll
        for (int mt = 0; mt < 2; mt++)
            #pragma unroll
            for (int nt = 0; nt < 4; nt++) {
                const int d = nt * 8 + c2;
                uint32_t h0, l0, h1, l1;
                split2(acc[mt][nt][0], acc[mt][nt][1], h0, l0);
                split2(acc[mt][nt][2], acc[mt][nt][3], h1, l1);
                *(uint32_t*)(ccp_hi + (mt * 16 + r) * ARS + d * 2)     = h0;
                *(uint32_t*)(ccp_lo + (mt * 16 + r) * ARS + d * 2)     = l0;
                *(uint32_t*)(ccp_hi + (mt * 16 + r + 8) * ARS + d * 2) = h1;
                *(uint32_t*)(ccp_lo + (mt * 16 + r + 8) * ARS + d * 2) = l1;
            }
        __syncwarp();
    }

    // ================= stage Q (pre-scaled in qkv epilogue) =================
    #pragma unroll
    for (int i = 0; i < 8; i++) {
        const int idx = lane + i * 32;
        const int rr = idx >> 2, cc = idx & 3;
        *(uint4*)(wbp + W_STGH + rr * ARS + cc * 16) =
            *(const uint4*)(g_qhi + qkvoff + idx * 8);
        *(uint4*)(wbp + W_STGL + rr * ARS + cc * 16) =
            *(const uint4*)(g_qlo + qkvoff + idx * 8);
    }
    __syncwarp();

    // ================= QK: M=64 N=48 K=32 =================
    float S[4][6][4] = {};
    #pragma unroll
    for (int kd = 0; kd < 2; kd++) {
        uint32_t Qh[4][4], Ql[4][4], Kh[3][4], Kl[3][4];
        #pragma unroll
        for (int mt = 0; mt < 4; mt++) {
            const uint32_t ao = (uint32_t)((mt * 16 + (lane & 15)) * ARS
                                           + kd * 32 + (lane >> 4) * 16);
            ldsm4(Qh[mt], stg_hi + ao);
            ldsm4(Ql[mt], stg_lo + ao);
        }
        const uint32_t bo = (uint32_t)(((lane & 7) + ((lane >> 4) << 3)) * ARS
                                       + ((lane >> 3) & 1) * 16 + kd * 32);
        #pragma unroll
        for (int jg = 0; jg < 3; jg++) {
            ldsm4(Kh[jg], kc_hi + jg * (16 * ARS) + bo);
            ldsm4(Kl[jg], kc_lo + jg * (16 * ARS) + bo);
        }
        #pragma unroll
        for (int mt = 0; mt < 4; mt++)
            #pragma unroll
            for (int jg = 0; jg < 3; jg++) {
                mma3(S[mt][jg * 2],     Qh[mt], Ql[mt],
                     Kh[jg][0], Kh[jg][1], Kl[jg][0], Kl[jg][1]);
                mma3(S[mt][jg * 2 + 1], Qh[mt], Ql[mt],
                     Kh[jg][2], Kh[jg][3], Kl[jg][2], Kl[jg][3]);
            }
    }

    // ================= softmax (no max subtraction; scores O(1)) =================
    float invA[4], invB[4];
    #pragma unroll
    for (int mt = 0; mt < 4; mt++) {
        float sA = 0.f, sB = 0.f;
        #pragma unroll
        for (int nt = 0; nt < 6; nt++) {
            S[mt][nt][0] = __expf(S[mt][nt][0]);
            S[mt][nt][1] = __expf(S[mt][nt][1]);
            S[mt][nt][2] = __expf(S[mt][nt][2]);
            S[mt][nt][3] = __expf(S[mt][nt][3]);
            sA += S[mt][nt][0] + S[mt][nt][1];
            sB += S[mt][nt][2] + S[mt][nt][3];
        }
        sA += __shfl_xor_sync(0xFFFFFFFFu, sA, 1);
        sA += __shfl_xor_sync(0xFFFFFFFFu, sA, 2);
        sB += __shfl_xor_sync(0xFFFFFFFFu, sB, 1);
        sB += __shfl_xor_sync(0xFFFFFFFFu, sB, 2);
        invA[mt] = 1.f / sA;
        invB[mt] = 1.f / sB;
    }

    // ================= PV: M=64 N=32 K=48 =================
    float O[4][4][4] = {};
    #pragma unroll
    for (int jg = 0; jg < 3; jg++) {
        uint32_t Ph[4][4], Pl[4][4];
        #pragma unroll
        for (int mt = 0; mt < 4; mt++) {
            split2(S[mt][2 * jg][0],     S[mt][2 * jg][1],     Ph[mt][0], Pl[mt][0]);
            split2(S[mt][2 * jg][2],     S[mt][2 * jg][3],     Ph[mt][1], Pl[mt][1]);
            split2(S[mt][2 * jg + 1][0], S[mt][2 * jg + 1][1], Ph[mt][2], Pl[mt][2]);
            split2(S[mt][2 * jg + 1][2], S[mt][2 * jg + 1][3], Ph[mt][3], Pl[mt][3]);
        }
        uint32_t Vh[2][4], Vl[2][4];
        const uint32_t vo = (uint32_t)((jg * 16 + (lane & 7) + ((lane >> 3) & 1) * 8) * ARS
                                       + (lane >> 4) * 16);
        #pragma unroll
        for (int dg = 0; dg < 2; dg++) {
            ldsm4t(Vh[dg], vc_hi + vo + dg * 32);
            ldsm4t(Vl[dg], vc_lo + vo + dg * 32);
        }
        #pragma unroll
        for (int mt = 0; mt < 4; mt++)
            #pragma unroll
            for (int dg = 0; dg < 2; dg++) {
                mma3(O[mt][dg * 2],     Ph[mt], Pl[mt],
                     Vh[dg][0], Vh[dg][1], Vl[dg][0], Vl[dg][1]);
                mma3(O[mt][dg * 2 + 1], Ph[mt], Pl[mt],
                     Vh[dg][2], Vh[dg][3], Vl[dg][2], Vl[dg][3]);
            }
    }

    // ================= normalize + out via smem restage (144B rows) =================
    __syncwarp();
    #pragma unroll
    for (int mt = 0; mt < 4; mt++)
        #pragma unroll
        for (int nt = 0; nt < 4; nt++) {
            const int cc = nt * 8 + c2;
            *(float2*)(wbp + (mt * 16 + r) * 144 + cc * 4) =
                make_float2(O[mt][nt][0] * invA[mt], O[mt][nt][1] * invA[mt]);
            *(float2*)(wbp + (mt * 16 + r + 8) * 144 + cc * 4) =
                make_float2(O[mt][nt][2] * invB[mt], O[mt][nt][3] * invB[mt]);
        }
    __syncwarp();
    #pragma unroll
    for (int rr = 0; rr < 2; rr++) {
        const int r2 = lane + rr * 32;
        float v[32];
        #pragma unroll
        for (int i = 0; i < 8; i++)
            *(float4*)(v + i * 4) = *(const float4*)(wbp + r2 * 144 + i * 16);
        uint32_t hw[16], lw[16];
        #pragma unroll
        for (int i = 0; i < 16; i++)
            split2(v[2 * i], v[2 * i + 1], hw[i], lw[i]);
        const size_t off = ((size_t)(w * NW + r2)) * CDIM + h * HD;
        #pragma unroll
        for (int i = 0; i < 4; i++) {
            *(uint4*)(g_aohi + off + i * 8) = *(uint4*)(hw + i * 4);
            *(uint4*)(g_aolo + off + i * 8) = *(uint4*)(lw + i * 4);
        }
    }
}

// =================================================================================
extern "C" void kernel_launch(void* const* d_in, const int* in_sizes, int n_in,
                              void* d_out, int out_size)
{
    (void)in_sizes; (void)n_in; (void)out_size;
    const float* x     = (const float*)d_in[0];
    const float* Wqkv  = (const float*)d_in[1];
    const float* bqkv  = (const float*)d_in[2];
    const float* E_k   = (const float*)d_in[3];
    const float* E_v   = (const float*)d_in[4];
    const float* kbank = (const float*)d_in[5];
    const float* vbank = (const float*)d_in[6];
    const float* Wp    = (const float*)d_in[7];
    const float* bp    = (const float*)d_in[8];
    float* out = (float*)d_out;

    cudaFuncSetAttribute(hmma_gemm<0>,
                         cudaFuncAttributeMaxDynamicSharedMemorySize, SMEMB);
    cudaFuncSetAttribute(hmma_gemm<1>,
                         cudaFuncAttributeMaxDynamicSharedMemorySize, SMEMB);
    cudaFuncSetAttribute(attn_kernel,
                         cudaFuncAttributeMaxDynamicSharedMemorySize, ATTN_SM);

    conv_x<<<8192, 256>>>(x);
    conv_w<<<1024, 64>>>(Wqkv, Wp);
    conv_eT<<<16, 128>>>(E_k, E_v);
    hmma_gemm<0><<<dim3(6, 512), 256, SMEMB>>>(bqkv, nullptr);
    attn_kernel<<<BW * 4, 64, ATTN_SM>>>(kbank, vbank);
    hmma_gemm<1><<<dim3(2, 512), 256, SMEMB>>>(bp, out);
}